// round 2
// baseline (speedup 1.0000x reference)
#include <cuda_runtime.h>
#include <math.h>

#define CCH   1024
#define HW    49
#define HW2   2401            // 49*49
#define CH    128             // channels per smem chunk
#define NCHUNK (CCH / CH)     // 8
#define NGROUP 4
#define CPG   (CH / NGROUP)   // 32 channels per group per chunk
#define NTHR  256

// Shared memory layout (floats):
//   buf  [2*CH*HW = 12544]  : q/k chunk (phase1) or v rows + staging (phase3)
//   part [NGROUP*HW2 = 9604]: phase1 partial logits / phase3 output staging
//   att  [HW2 = 2401]       : attention matrix
//   red  [8]                : block-reduce scratch
#define SM_FLOATS (2*CH*HW + NGROUP*HW2 + HW2 + 8)   // 24557 floats = 98228 B

__global__ __launch_bounds__(NTHR, 2)
void pam_kernel(const float* __restrict__ vin,
                const float* __restrict__ qin,
                const float* __restrict__ kin,
                float* __restrict__ out)
{
    extern __shared__ float smem[];
    float* buf  = smem;                    // 12544 floats
    float* part = buf  + 2*CH*HW;          // 9604 floats
    float* att  = part + NGROUP*HW2;       // 2401 floats
    float* red  = att  + HW2;              // 8 floats

    const int b = blockIdx.x;
    const int t = threadIdx.x;

    const float* qb = qin + (size_t)b * CCH * HW;
    const float* kb = kin + (size_t)b * CCH * HW;
    const float* vb = vin + (size_t)b * CCH * HW;
    float*       ob = out + (size_t)b * CCH * HW;

    // ================= Phase 1: logits = q^T k ==================
    const int g    = t >> 6;        // channel-split group 0..3
    const int slot = t & 63;        // tile slot within group
    const int ti   = slot / 7;      // i-tile (valid when slot<49)
    const int tj   = slot % 7;      // j-tile
    const bool active = (slot < 49);

    float acc[49];
#pragma unroll
    for (int p = 0; p < 49; ++p) acc[p] = 0.f;

    float* q_s = buf;               // CH*HW
    float* k_s = buf + CH*HW;       // CH*HW

    for (int ch = 0; ch < NCHUNK; ++ch) {
        // coalesced float4 loads of this 128-channel chunk of q and k
        const float4* q4 = (const float4*)(qb + ch * CH * HW);
        const float4* k4 = (const float4*)(kb + ch * CH * HW);
        float4* qs4 = (float4*)q_s;
        float4* ks4 = (float4*)k_s;
#pragma unroll
        for (int idx = t; idx < (CH*HW)/4; idx += NTHR) {
            qs4[idx] = q4[idx];
            ks4[idx] = k4[idx];
        }
        __syncthreads();

        if (active) {
            const float* qp = q_s + g * CPG * HW + ti * 7;
            const float* kp = k_s + g * CPG * HW + tj * 7;
#pragma unroll 2
            for (int cc = 0; cc < CPG; ++cc) {
                float qv[7], kv[7];
#pragma unroll
                for (int u = 0; u < 7; ++u) qv[u] = qp[u];
#pragma unroll
                for (int u = 0; u < 7; ++u) kv[u] = kp[u];
#pragma unroll
                for (int a = 0; a < 7; ++a)
#pragma unroll
                    for (int j = 0; j < 7; ++j)
                        acc[a*7 + j] += qv[a] * kv[j];
                qp += HW;
                kp += HW;
            }
        }
        __syncthreads();
    }

    // write per-group partial logits
    if (active) {
#pragma unroll
        for (int a = 0; a < 7; ++a)
#pragma unroll
            for (int j = 0; j < 7; ++j)
                part[g*HW2 + (ti*7 + a)*HW + (tj*7 + j)] = acc[a*7 + j];
    }
    __syncthreads();

    // ================= Phase 2: flat softmax over 2401 ==========
    float lmax = -INFINITY;
    for (int p = t; p < HW2; p += NTHR) {
        float s = part[p] + part[HW2 + p] + part[2*HW2 + p] + part[3*HW2 + p];
        att[p] = s;
        lmax = fmaxf(lmax, s);
    }
#pragma unroll
    for (int o = 16; o > 0; o >>= 1)
        lmax = fmaxf(lmax, __shfl_xor_sync(0xFFFFFFFFu, lmax, o));
    if ((t & 31) == 0) red[t >> 5] = lmax;
    __syncthreads();
    float bmax = red[0];
#pragma unroll
    for (int w = 1; w < 8; ++w) bmax = fmaxf(bmax, red[w]);

    float lsum = 0.f;
    for (int p = t; p < HW2; p += NTHR) {
        float e = __expf(att[p] - bmax);
        att[p] = e;
        lsum += e;
    }
    __syncthreads();   // everyone done reading red (max stage)
#pragma unroll
    for (int o = 16; o > 0; o >>= 1)
        lsum += __shfl_xor_sync(0xFFFFFFFFu, lsum, o);
    if ((t & 31) == 0) red[t >> 5] = lsum;
    __syncthreads();
    float bsum = red[0];
#pragma unroll
    for (int w = 1; w < 8; ++w) bsum += red[w];
    const float inv = 1.f / bsum;
    for (int p = t; p < HW2; p += NTHR) att[p] *= inv;
    // (att reads in phase 3 happen only after the next __syncthreads)

    // ================= Phase 3: out = v @ att + v ===============
    float* v_s = buf;     // 128*49 floats per pass
    float* o_s = part;    // 128*49 floats staging

    const int jt    = t & 7;    // j-tile 0..6 active, 7 idle
    const int ctile = t >> 3;   // 0..31 -> 4 rows each

    for (int pass = 0; pass < CCH / CH; ++pass) {
        const float4* v4 = (const float4*)(vb + pass * CH * HW);
        float4* vs4 = (float4*)v_s;
#pragma unroll
        for (int idx = t; idx < (CH*HW)/4; idx += NTHR)
            vs4[idx] = v4[idx];
        __syncthreads();

        if (jt < 7) {
            float oacc[4][7];
#pragma unroll
            for (int r = 0; r < 4; ++r)
#pragma unroll
                for (int j = 0; j < 7; ++j) oacc[r][j] = 0.f;

            const float* ap = att + jt * 7;
#pragma unroll 2
            for (int i = 0; i < HW; ++i) {
                float av[7];
#pragma unroll
                for (int j = 0; j < 7; ++j) av[j] = ap[i*HW + j];
#pragma unroll
                for (int r = 0; r < 4; ++r) {
                    float vv = v_s[(ctile*4 + r)*HW + i];
#pragma unroll
                    for (int j = 0; j < 7; ++j)
                        oacc[r][j] += vv * av[j];
                }
            }
#pragma unroll
            for (int r = 0; r < 4; ++r) {
                int cl = ctile*4 + r;
#pragma unroll
                for (int j = 0; j < 7; ++j) {
                    int col = jt*7 + j;
                    o_s[cl*HW + col] = oacc[r][j] + v_s[cl*HW + col];
                }
            }
        }
        __syncthreads();

        float4* od4 = (float4*)(ob + pass * CH * HW);
        const float4* os4 = (const float4*)o_s;
#pragma unroll
        for (int idx = t; idx < (CH*HW)/4; idx += NTHR)
            od4[idx] = os4[idx];
        __syncthreads();
    }
}

extern "C" void kernel_launch(void* const* d_in, const int* in_sizes, int n_in,
                              void* d_out, int out_size)
{
    const float* v = (const float*)d_in[0];   // v1
    const float* q = (const float*)d_in[1];   // q1
    const float* k = (const float*)d_in[2];   // k1
    float* out = (float*)d_out;

    const int B = in_sizes[0] / (CCH * HW);
    const size_t smem_bytes = SM_FLOATS * sizeof(float);

    cudaFuncSetAttribute(pam_kernel,
                         cudaFuncAttributeMaxDynamicSharedMemorySize,
                         (int)smem_bytes);
    pam_kernel<<<B, NTHR, smem_bytes>>>(v, q, k, out);
}